// round 1
// baseline (speedup 1.0000x reference)
#include <cuda_runtime.h>

#define NN 50000
#define EE 800000
#define DD 128
#define GG 128
#define CC 10

// ---------------- static device scratch (no cudaMalloc allowed) ----------------
__device__ float g_buf[3][(size_t)NN * DD];   // feature buffers
__device__ int   g_cnt[NN];
__device__ int   g_rowptr[NN + 1];
__device__ int   g_cursor[NN];
__device__ int   g_src[EE];
__device__ float g_dinv[NN];
__device__ float g_sums[GG * DD];
__device__ float g_cntf[GG];

// ---------------- setup kernels ----------------
__global__ void k_zero() {
    int i = blockIdx.x * blockDim.x + threadIdx.x;
    if (i < NN) g_cnt[i] = 0;
    if (i < GG * DD) g_sums[i] = 0.f;
    if (i < GG) g_cntf[i] = 0.f;
}

__global__ void k_count(const int* __restrict__ col) {
    int e = blockIdx.x * blockDim.x + threadIdx.x;
    if (e < EE) atomicAdd(&g_cnt[col[e]], 1);
}

// single-block exclusive scan over NN counts -> rowptr/cursor, plus dinv
__global__ void k_scan() {
    __shared__ int partial[1024];
    const int T = 1024;
    int t = threadIdx.x;
    const int CH = (NN + T - 1) / T;
    int base = t * CH;
    int s = 0;
    for (int i = 0; i < CH; i++) {
        int idx = base + i;
        if (idx < NN) s += g_cnt[idx];
    }
    partial[t] = s;
    __syncthreads();
    for (int off = 1; off < T; off <<= 1) {
        int v = (t >= off) ? partial[t - off] : 0;
        __syncthreads();
        partial[t] += v;
        __syncthreads();
    }
    int run = (t == 0) ? 0 : partial[t - 1];
    for (int i = 0; i < CH; i++) {
        int idx = base + i;
        if (idx < NN) {
            g_rowptr[idx] = run;
            g_cursor[idx] = run;
            int c = g_cnt[idx];
            run += c;
            g_dinv[idx] = rsqrtf((float)c + 1.0f);  // +1 self loop
        }
    }
    if (t == T - 1) g_rowptr[NN] = partial[T - 1];
}

__global__ void k_fill(const int* __restrict__ row, const int* __restrict__ col) {
    int e = blockIdx.x * blockDim.x + threadIdx.x;
    if (e < EE) {
        int c = col[e];
        int p = atomicAdd(&g_cursor[c], 1);
        g_src[p] = row[e];
    }
}

// ---------------- gather kernels (warp per node, float4 lanes) ----------------
__global__ void k_gather_x(const float* __restrict__ x) {
    int gw = (blockIdx.x * blockDim.x + threadIdx.x) >> 5;
    if (gw >= NN) return;
    int lane = threadIdx.x & 31;
    int beg = g_rowptr[gw], end = g_rowptr[gw + 1];
    float4 acc = make_float4(0.f, 0.f, 0.f, 0.f);
    int k = beg;
    for (; k + 4 <= end; k += 4) {
        int j0 = g_src[k], j1 = g_src[k + 1], j2 = g_src[k + 2], j3 = g_src[k + 3];
        float4 v0 = *(const float4*)&x[(size_t)j0 * DD + lane * 4];
        float4 v1 = *(const float4*)&x[(size_t)j1 * DD + lane * 4];
        float4 v2 = *(const float4*)&x[(size_t)j2 * DD + lane * 4];
        float4 v3 = *(const float4*)&x[(size_t)j3 * DD + lane * 4];
        acc.x += (v0.x + v1.x) + (v2.x + v3.x);
        acc.y += (v0.y + v1.y) + (v2.y + v3.y);
        acc.z += (v0.z + v1.z) + (v2.z + v3.z);
        acc.w += (v0.w + v1.w) + (v2.w + v3.w);
    }
    for (; k < end; k++) {
        int j = g_src[k];
        float4 v = *(const float4*)&x[(size_t)j * DD + lane * 4];
        acc.x += v.x; acc.y += v.y; acc.z += v.z; acc.w += v.w;
    }
    *(float4*)&g_buf[0][(size_t)gw * DD + lane * 4] = acc;
}

// h_out[i] = maybe_relu( dinv[i]*(sum_nbr hps[j] + hps[i]) + b )
__global__ void k_gather_norm(int in_sel, int out_sel, const float* __restrict__ bias, int do_relu) {
    int gw = (blockIdx.x * blockDim.x + threadIdx.x) >> 5;
    if (gw >= NN) return;
    int lane = threadIdx.x & 31;
    const float* __restrict__ hps = g_buf[in_sel];
    int beg = g_rowptr[gw], end = g_rowptr[gw + 1];
    float4 acc = make_float4(0.f, 0.f, 0.f, 0.f);
    int k = beg;
    for (; k + 4 <= end; k += 4) {
        int j0 = g_src[k], j1 = g_src[k + 1], j2 = g_src[k + 2], j3 = g_src[k + 3];
        float4 v0 = *(const float4*)&hps[(size_t)j0 * DD + lane * 4];
        float4 v1 = *(const float4*)&hps[(size_t)j1 * DD + lane * 4];
        float4 v2 = *(const float4*)&hps[(size_t)j2 * DD + lane * 4];
        float4 v3 = *(const float4*)&hps[(size_t)j3 * DD + lane * 4];
        acc.x += (v0.x + v1.x) + (v2.x + v3.x);
        acc.y += (v0.y + v1.y) + (v2.y + v3.y);
        acc.z += (v0.z + v1.z) + (v2.z + v3.z);
        acc.w += (v0.w + v1.w) + (v2.w + v3.w);
    }
    for (; k < end; k++) {
        int j = g_src[k];
        float4 v = *(const float4*)&hps[(size_t)j * DD + lane * 4];
        acc.x += v.x; acc.y += v.y; acc.z += v.z; acc.w += v.w;
    }
    float4 self = *(const float4*)&hps[(size_t)gw * DD + lane * 4];
    float di = g_dinv[gw];
    float4 bb = *(const float4*)&bias[lane * 4];
    float4 o;
    o.x = di * (acc.x + self.x) + bb.x;
    o.y = di * (acc.y + self.y) + bb.y;
    o.z = di * (acc.z + self.z) + bb.z;
    o.w = di * (acc.w + self.w) + bb.w;
    if (do_relu) {
        o.x = fmaxf(o.x, 0.f); o.y = fmaxf(o.y, 0.f);
        o.z = fmaxf(o.z, 0.f); o.w = fmaxf(o.w, 0.f);
    }
    *(float4*)&g_buf[out_sel][(size_t)gw * DD + lane * 4] = o;
}

// ---------------- GEMM kernels ----------------
// conv1: g_buf[1] = relu(g_buf[0] @ W1r^T + x @ W1x^T + b1)
// Shared layout: Wr[d][h] (pad 132), Wx[d][h], Aa[d][r] (pad 68), Ax[d][r]
#define SMEM1 ((2 * 128 * 132 + 2 * 128 * 68) * 4)
__global__ __launch_bounds__(512, 1) void k_gemm_conv1(
    const float* __restrict__ x, const float* __restrict__ W1r,
    const float* __restrict__ W1x, const float* __restrict__ b1)
{
    extern __shared__ float sh[];
    float* Wr = sh;
    float* Wx = Wr + 128 * 132;
    float* Aa = Wx + 128 * 132;
    float* Ax = Aa + 128 * 68;
    int tid = threadIdx.x;
    for (int idx = tid; idx < DD * DD; idx += 512) {
        int h = idx >> 7, d = idx & 127;
        Wr[d * 132 + h] = W1r[idx];
        Wx[d * 132 + h] = W1x[idx];
    }
    int row0 = blockIdx.x * 64;
    for (int idx = tid; idx < 64 * DD; idx += 512) {
        int r = idx >> 7, d = idx & 127;
        int gr = row0 + r;
        float va = 0.f, vx = 0.f;
        if (gr < NN) {
            va = g_buf[0][(size_t)gr * DD + d];
            vx = x[(size_t)gr * DD + d];
        }
        Aa[d * 68 + r] = va;
        Ax[d * 68 + r] = vx;
    }
    __syncthreads();
    int tx = tid & 31, ty = tid >> 5;  // ty 0..15 -> 4 rows each
    float acc[4][4];
#pragma unroll
    for (int r = 0; r < 4; r++)
#pragma unroll
        for (int c = 0; c < 4; c++) acc[r][c] = 0.f;
#pragma unroll 2
    for (int d = 0; d < DD; d++) {
        float4 wr = *(const float4*)&Wr[d * 132 + tx * 4];
        float4 wx = *(const float4*)&Wx[d * 132 + tx * 4];
        float4 a4 = *(const float4*)&Aa[d * 68 + ty * 4];
        float4 x4 = *(const float4*)&Ax[d * 68 + ty * 4];
        float av[4] = {a4.x, a4.y, a4.z, a4.w};
        float xv[4] = {x4.x, x4.y, x4.z, x4.w};
#pragma unroll
        for (int r = 0; r < 4; r++) {
            float a = av[r], b = xv[r];
            acc[r][0] += a * wr.x; acc[r][0] += b * wx.x;
            acc[r][1] += a * wr.y; acc[r][1] += b * wx.y;
            acc[r][2] += a * wr.z; acc[r][2] += b * wx.z;
            acc[r][3] += a * wr.w; acc[r][3] += b * wx.w;
        }
    }
    float4 bias = *(const float4*)&b1[tx * 4];
#pragma unroll
    for (int r = 0; r < 4; r++) {
        int gr = row0 + ty * 4 + r;
        if (gr < NN) {
            float4 o;
            o.x = fmaxf(acc[r][0] + bias.x, 0.f);
            o.y = fmaxf(acc[r][1] + bias.y, 0.f);
            o.z = fmaxf(acc[r][2] + bias.z, 0.f);
            o.w = fmaxf(acc[r][3] + bias.w, 0.f);
            *(float4*)&g_buf[1][(size_t)gr * DD + tx * 4] = o;
        }
    }
}

// g_buf[out] = dinv[i] * (g_buf[in] @ W^T)
#define SMEM2 ((128 * 132 + 128 * 68) * 4)
__global__ __launch_bounds__(512, 2) void k_gemm_scaled(
    int in_sel, const float* __restrict__ W, int out_sel)
{
    extern __shared__ float sh[];
    float* Wt = sh;
    float* At = Wt + 128 * 132;
    int tid = threadIdx.x;
    const float* __restrict__ A = g_buf[in_sel];
    for (int idx = tid; idx < DD * DD; idx += 512) {
        int h = idx >> 7, d = idx & 127;
        Wt[d * 132 + h] = W[idx];
    }
    int row0 = blockIdx.x * 64;
    for (int idx = tid; idx < 64 * DD; idx += 512) {
        int r = idx >> 7, d = idx & 127;
        int gr = row0 + r;
        float va = 0.f;
        if (gr < NN) va = A[(size_t)gr * DD + d];
        At[d * 68 + r] = va;
    }
    __syncthreads();
    int tx = tid & 31, ty = tid >> 5;
    float acc[4][4];
#pragma unroll
    for (int r = 0; r < 4; r++)
#pragma unroll
        for (int c = 0; c < 4; c++) acc[r][c] = 0.f;
#pragma unroll 2
    for (int d = 0; d < DD; d++) {
        float4 w4 = *(const float4*)&Wt[d * 132 + tx * 4];
        float4 a4 = *(const float4*)&At[d * 68 + ty * 4];
        float av[4] = {a4.x, a4.y, a4.z, a4.w};
#pragma unroll
        for (int r = 0; r < 4; r++) {
            float a = av[r];
            acc[r][0] += a * w4.x;
            acc[r][1] += a * w4.y;
            acc[r][2] += a * w4.z;
            acc[r][3] += a * w4.w;
        }
    }
#pragma unroll
    for (int r = 0; r < 4; r++) {
        int gr = row0 + ty * 4 + r;
        if (gr < NN) {
            float di = g_dinv[gr];
            float4 o;
            o.x = acc[r][0] * di;
            o.y = acc[r][1] * di;
            o.z = acc[r][2] * di;
            o.w = acc[r][3] * di;
            *(float4*)&g_buf[out_sel][(size_t)gr * DD + tx * 4] = o;
        }
    }
}

// ---------------- pooling (batch is sorted: run-accumulate, flush at boundary) ----------------
__global__ void k_pool(const int* __restrict__ batch, int sel) {
    const float* __restrict__ h = g_buf[sel];
    int start = blockIdx.x * 512;
    if (start >= NN) return;
    int endr = min(start + 512, NN);
    int d = threadIdx.x;  // 128 threads
    int cur = batch[start];
    float run = 0.f, crun = 0.f;
    for (int r = start; r < endr; r++) {
        int b = batch[r];
        if (b != cur) {
            atomicAdd(&g_sums[cur * DD + d], run);
            if (d == 0) atomicAdd(&g_cntf[cur], crun);
            run = 0.f; crun = 0.f; cur = b;
        }
        run += h[(size_t)r * DD + d];
        crun += 1.f;
    }
    atomicAdd(&g_sums[cur * DD + d], run);
    if (d == 0) atomicAdd(&g_cntf[cur], crun);
}

// ---------------- finalize: mean, L2-normalize, classifier with row-normalized Wl ----------------
__global__ void k_final(const float* __restrict__ Wl, const float* __restrict__ bl,
                        float* __restrict__ out)
{
    int g = blockIdx.x;
    int d = threadIdx.x;
    __shared__ float red[128];
    __shared__ float xsh[128];
    float c = g_cntf[g];
    float pooled = g_sums[g * DD + d] / fmaxf(c, 1.f);
    red[d] = pooled * pooled;
    __syncthreads();
    for (int s = 64; s > 0; s >>= 1) {
        if (d < s) red[d] += red[d + s];
        __syncthreads();
    }
    float inv = 1.f / fmaxf(sqrtf(red[0]), 1e-12f);
    float xn = pooled * inv;
    out[g * DD + d] = xn;
    xsh[d] = xn;
    __syncthreads();
    if (d < CC) {
        float dot = 0.f, w2 = 0.f;
        for (int k = 0; k < DD; k++) {
            float w = Wl[d * DD + k];
            dot += xsh[k] * w;
            w2 += w * w;
        }
        out[GG * DD + g * CC + d] = dot / fmaxf(sqrtf(w2), 1e-12f) + bl[d];
    }
}

// ---------------- launch ----------------
extern "C" void kernel_launch(void* const* d_in, const int* in_sizes, int n_in,
                              void* d_out, int out_size)
{
    const float* x   = (const float*)d_in[0];
    const int*   ei  = (const int*)d_in[1];
    const int*   bat = (const int*)d_in[2];
    const float* W1r = (const float*)d_in[3];
    const float* b1  = (const float*)d_in[4];
    const float* W1x = (const float*)d_in[5];
    const float* W2  = (const float*)d_in[6];
    const float* b2  = (const float*)d_in[7];
    const float* W3  = (const float*)d_in[8];
    const float* b3  = (const float*)d_in[9];
    const float* Wl  = (const float*)d_in[10];
    const float* bl  = (const float*)d_in[11];
    float* out = (float*)d_out;
    const int* row = ei;
    const int* col = ei + EE;

    cudaFuncSetAttribute(k_gemm_conv1, cudaFuncAttributeMaxDynamicSharedMemorySize, SMEM1);
    cudaFuncSetAttribute(k_gemm_scaled, cudaFuncAttributeMaxDynamicSharedMemorySize, SMEM2);

    int gwarps = (NN * 32 + 255) / 256;   // gather: warp per node
    int gblocks = (NN + 63) / 64;         // gemm: 64 rows per block

    k_zero<<<(NN + 255) / 256, 256>>>();
    k_count<<<(EE + 255) / 256, 256>>>(col);
    k_scan<<<1, 1024>>>();
    k_fill<<<(EE + 255) / 256, 256>>>(row, col);
    k_gather_x<<<gwarps, 256>>>(x);                          // buf0 = sum x[nbr]
    k_gemm_conv1<<<gblocks, 512, SMEM1>>>(x, W1r, W1x, b1);  // buf1 = h1
    k_gemm_scaled<<<gblocks, 512, SMEM2>>>(1, W2, 0);        // buf0 = dinv*(h1@W2^T)
    k_gather_norm<<<gwarps, 256>>>(0, 2, b2, 1);             // buf2 = h2
    k_gemm_scaled<<<gblocks, 512, SMEM2>>>(2, W3, 0);        // buf0 = dinv*(h2@W3^T)
    k_gather_norm<<<gwarps, 256>>>(0, 1, b3, 0);             // buf1 = h3
    k_pool<<<(NN + 511) / 512, 128>>>(bat, 1);
    k_final<<<GG, 128>>>(Wl, bl, out);
}

// round 3
// speedup vs baseline: 1.3780x; 1.3780x over previous
#include <cuda_runtime.h>
#include <cstdint>

#define NN 50000
#define EE 800000
#define DD 128
#define GG 128
#define CC 10

// ---------------- static device scratch (no cudaMalloc allowed) ----------------
__device__ float g_buf[3][(size_t)NN * DD];   // feature buffers
__device__ int   g_cnt[NN];
__device__ int   g_rowptr[NN + 1];
__device__ int   g_cursor[NN];
__device__ int   g_src[EE];
__device__ float g_dinv[NN];
__device__ float g_sums[GG * DD];
__device__ float g_cntf[GG];

// ---------------- helpers ----------------
__device__ __forceinline__ float ftf32(float x) {
    uint32_t u;
    asm("cvt.rn.tf32.f32 %0, %1;" : "=r"(u) : "f"(x));
    return __uint_as_float(u);
}
__device__ __forceinline__ void mma_tf32(float c[4],
                                         uint32_t a0, uint32_t a1, uint32_t a2, uint32_t a3,
                                         uint32_t b0, uint32_t b1) {
    asm volatile(
        "mma.sync.aligned.m16n8k8.row.col.f32.tf32.tf32.f32 "
        "{%0,%1,%2,%3}, {%4,%5,%6,%7}, {%8,%9}, {%0,%1,%2,%3};"
        : "+f"(c[0]), "+f"(c[1]), "+f"(c[2]), "+f"(c[3])
        : "r"(a0), "r"(a1), "r"(a2), "r"(a3), "r"(b0), "r"(b1));
}

// ---------------- setup kernels ----------------
__global__ void k_zero() {
    int i = blockIdx.x * blockDim.x + threadIdx.x;
    if (i < NN) g_cnt[i] = 0;
    if (i < GG * DD) g_sums[i] = 0.f;
    if (i < GG) g_cntf[i] = 0.f;
}

__global__ void k_count(const int* __restrict__ col) {
    int e = blockIdx.x * blockDim.x + threadIdx.x;
    if (e < EE) atomicAdd(&g_cnt[col[e]], 1);
}

__global__ void k_scan() {
    __shared__ int partial[1024];
    const int T = 1024;
    int t = threadIdx.x;
    const int CH = (NN + T - 1) / T;
    int base = t * CH;
    int s = 0;
    for (int i = 0; i < CH; i++) {
        int idx = base + i;
        if (idx < NN) s += g_cnt[idx];
    }
    partial[t] = s;
    __syncthreads();
    for (int off = 1; off < T; off <<= 1) {
        int v = (t >= off) ? partial[t - off] : 0;
        __syncthreads();
        partial[t] += v;
        __syncthreads();
    }
    int run = (t == 0) ? 0 : partial[t - 1];
    for (int i = 0; i < CH; i++) {
        int idx = base + i;
        if (idx < NN) {
            g_rowptr[idx] = run;
            g_cursor[idx] = run;
            int c = g_cnt[idx];
            run += c;
            g_dinv[idx] = rsqrtf((float)c + 1.0f);
        }
    }
    if (t == T - 1) g_rowptr[NN] = partial[T - 1];
}

__global__ void k_fill(const int* __restrict__ row, const int* __restrict__ col) {
    int e = blockIdx.x * blockDim.x + threadIdx.x;
    if (e < EE) {
        int c = col[e];
        int p = atomicAdd(&g_cursor[c], 1);
        g_src[p] = row[e];
    }
}

// ---------------- gather kernels ----------------
__global__ void k_gather_x(const float* __restrict__ x) {
    int gw = (blockIdx.x * blockDim.x + threadIdx.x) >> 5;
    if (gw >= NN) return;
    int lane = threadIdx.x & 31;
    int beg = g_rowptr[gw], end = g_rowptr[gw + 1];
    float4 acc = make_float4(0.f, 0.f, 0.f, 0.f);
    int k = beg;
    for (; k + 4 <= end; k += 4) {
        int j0 = g_src[k], j1 = g_src[k + 1], j2 = g_src[k + 2], j3 = g_src[k + 3];
        float4 v0 = *(const float4*)&x[(size_t)j0 * DD + lane * 4];
        float4 v1 = *(const float4*)&x[(size_t)j1 * DD + lane * 4];
        float4 v2 = *(const float4*)&x[(size_t)j2 * DD + lane * 4];
        float4 v3 = *(const float4*)&x[(size_t)j3 * DD + lane * 4];
        acc.x += (v0.x + v1.x) + (v2.x + v3.x);
        acc.y += (v0.y + v1.y) + (v2.y + v3.y);
        acc.z += (v0.z + v1.z) + (v2.z + v3.z);
        acc.w += (v0.w + v1.w) + (v2.w + v3.w);
    }
    for (; k < end; k++) {
        int j = g_src[k];
        float4 v = *(const float4*)&x[(size_t)j * DD + lane * 4];
        acc.x += v.x; acc.y += v.y; acc.z += v.z; acc.w += v.w;
    }
    *(float4*)&g_buf[0][(size_t)gw * DD + lane * 4] = acc;
}

__global__ void k_gather_norm(int in_sel, int out_sel, const float* __restrict__ bias, int do_relu) {
    int gw = (blockIdx.x * blockDim.x + threadIdx.x) >> 5;
    if (gw >= NN) return;
    int lane = threadIdx.x & 31;
    const float* __restrict__ hps = g_buf[in_sel];
    int beg = g_rowptr[gw], end = g_rowptr[gw + 1];
    float4 acc = make_float4(0.f, 0.f, 0.f, 0.f);
    int k = beg;
    for (; k + 4 <= end; k += 4) {
        int j0 = g_src[k], j1 = g_src[k + 1], j2 = g_src[k + 2], j3 = g_src[k + 3];
        float4 v0 = *(const float4*)&hps[(size_t)j0 * DD + lane * 4];
        float4 v1 = *(const float4*)&hps[(size_t)j1 * DD + lane * 4];
        float4 v2 = *(const float4*)&hps[(size_t)j2 * DD + lane * 4];
        float4 v3 = *(const float4*)&hps[(size_t)j3 * DD + lane * 4];
        acc.x += (v0.x + v1.x) + (v2.x + v3.x);
        acc.y += (v0.y + v1.y) + (v2.y + v3.y);
        acc.z += (v0.z + v1.z) + (v2.z + v3.z);
        acc.w += (v0.w + v1.w) + (v2.w + v3.w);
    }
    for (; k < end; k++) {
        int j = g_src[k];
        float4 v = *(const float4*)&hps[(size_t)j * DD + lane * 4];
        acc.x += v.x; acc.y += v.y; acc.z += v.z; acc.w += v.w;
    }
    float4 self = *(const float4*)&hps[(size_t)gw * DD + lane * 4];
    float di = g_dinv[gw];
    float4 bb = *(const float4*)&bias[lane * 4];
    float4 o;
    o.x = di * (acc.x + self.x) + bb.x;
    o.y = di * (acc.y + self.y) + bb.y;
    o.z = di * (acc.z + self.z) + bb.z;
    o.w = di * (acc.w + self.w) + bb.w;
    if (do_relu) {
        o.x = fmaxf(o.x, 0.f); o.y = fmaxf(o.y, 0.f);
        o.z = fmaxf(o.z, 0.f); o.w = fmaxf(o.w, 0.f);
    }
    *(float4*)&g_buf[out_sel][(size_t)gw * DD + lane * 4] = o;
}

// ---------------- tf32 mma.sync GEMM ----------------
// C[128 rows/block][128] = sum_p A_p @ W_p^T; epilogue (+bias)(relu)(×dinv) -> g_buf[out_sel]
// SMEM: As[128][132], Ws[128][132] fp32 (tf32-rounded). 132-pad => conflict-free frags.
#define GSMEM (2 * 128 * 132 * 4)
__global__ __launch_bounds__(256, 1) void k_gemm_mma(
    const float* __restrict__ x_ext,   // A1 for conv1 (P=2)
    int a0_sel,
    const float* __restrict__ W0,
    const float* __restrict__ W1,      // for P=2
    const float* __restrict__ bias,    // nullable
    int use_dinv, int relu, int P,
    int out_sel)
{
    extern __shared__ float sh[];
    float* As = sh;                 // 128*132
    float* Ws = sh + 128 * 132;

    int tid = threadIdx.x;
    int wid = tid >> 5, lane = tid & 31;
    int g = lane >> 2, t = lane & 3;
    int wm = wid & 3, wn = wid >> 2;     // warp tile: rows wm*32..+31, cols wn*64..+63
    int row0 = blockIdx.x * 128;

    float c[2][8][4];
#pragma unroll
    for (int ms = 0; ms < 2; ms++)
#pragma unroll
        for (int ns = 0; ns < 8; ns++)
#pragma unroll
            for (int j = 0; j < 4; j++) c[ms][ns][j] = 0.f;

    for (int p = 0; p < P; p++) {
        const float* Ap = p ? x_ext : g_buf[a0_sel];
        const float* Wp = p ? W1 : W0;
        // fill W
        for (int idx = tid; idx < 4096; idx += 256) {
            int n = idx >> 5, k4 = idx & 31;
            float4 v = *(const float4*)&Wp[n * DD + k4 * 4];
            v.x = ftf32(v.x); v.y = ftf32(v.y); v.z = ftf32(v.z); v.w = ftf32(v.w);
            *(float4*)&Ws[n * 132 + k4 * 4] = v;
        }
        // fill A
        for (int idx = tid; idx < 4096; idx += 256) {
            int r = idx >> 5, k4 = idx & 31;
            int gr = row0 + r;
            float4 v = make_float4(0.f, 0.f, 0.f, 0.f);
            if (gr < NN) {
                v = *(const float4*)&Ap[(size_t)gr * DD + k4 * 4];
                v.x = ftf32(v.x); v.y = ftf32(v.y); v.z = ftf32(v.z); v.w = ftf32(v.w);
            }
            *(float4*)&As[r * 132 + k4 * 4] = v;
        }
        __syncthreads();

#pragma unroll 2
        for (int kk = 0; kk < 16; kk++) {
            uint32_t a[2][4];
#pragma unroll
            for (int ms = 0; ms < 2; ms++) {
                const float* ap = &As[(wm * 32 + ms * 16 + g) * 132 + kk * 8 + t];
                a[ms][0] = __float_as_uint(ap[0]);
                a[ms][1] = __float_as_uint(ap[8 * 132]);
                a[ms][2] = __float_as_uint(ap[4]);
                a[ms][3] = __float_as_uint(ap[8 * 132 + 4]);
            }
            uint32_t b[8][2];
#pragma unroll
            for (int ns = 0; ns < 8; ns++) {
                const float* bp = &Ws[(wn * 64 + ns * 8 + g) * 132 + kk * 8 + t];
                b[ns][0] = __float_as_uint(bp[0]);
                b[ns][1] = __float_as_uint(bp[4]);
            }
#pragma unroll
            for (int ms = 0; ms < 2; ms++)
#pragma unroll
                for (int ns = 0; ns < 8; ns++)
                    mma_tf32(c[ms][ns], a[ms][0], a[ms][1], a[ms][2], a[ms][3],
                             b[ns][0], b[ns][1]);
        }
        __syncthreads();
    }

    // epilogue
    float* out = g_buf[out_sel];
#pragma unroll
    for (int ms = 0; ms < 2; ms++) {
        int r_lo = row0 + wm * 32 + ms * 16 + g;
        int r_hi = r_lo + 8;
        float di_lo = 1.f, di_hi = 1.f;
        if (use_dinv) {
            if (r_lo < NN) di_lo = g_dinv[r_lo];
            if (r_hi < NN) di_hi = g_dinv[r_hi];
        }
#pragma unroll
        for (int ns = 0; ns < 8; ns++) {
            int col = wn * 64 + ns * 8 + 2 * t;
            float b0 = 0.f, b1 = 0.f;
            if (bias) { b0 = bias[col]; b1 = bias[col + 1]; }
            float f0 = c[ms][ns][0] + b0, f1 = c[ms][ns][1] + b1;
            float f2 = c[ms][ns][2] + b0, f3 = c[ms][ns][3] + b1;
            if (relu) {
                f0 = fmaxf(f0, 0.f); f1 = fmaxf(f1, 0.f);
                f2 = fmaxf(f2, 0.f); f3 = fmaxf(f3, 0.f);
            }
            if (r_lo < NN) *(float2*)&out[(size_t)r_lo * DD + col] = make_float2(f0 * di_lo, f1 * di_lo);
            if (r_hi < NN) *(float2*)&out[(size_t)r_hi * DD + col] = make_float2(f2 * di_hi, f3 * di_hi);
        }
    }
}

// ---------------- pooling ----------------
__global__ void k_pool(const int* __restrict__ batch, int sel) {
    const float* __restrict__ h = g_buf[sel];
    int start = blockIdx.x * 512;
    if (start >= NN) return;
    int endr = min(start + 512, NN);
    int d = threadIdx.x;
    int cur = batch[start];
    float run = 0.f, crun = 0.f;
    for (int r = start; r < endr; r++) {
        int b = batch[r];
        if (b != cur) {
            atomicAdd(&g_sums[cur * DD + d], run);
            if (d == 0) atomicAdd(&g_cntf[cur], crun);
            run = 0.f; crun = 0.f; cur = b;
        }
        run += h[(size_t)r * DD + d];
        crun += 1.f;
    }
    atomicAdd(&g_sums[cur * DD + d], run);
    if (d == 0) atomicAdd(&g_cntf[cur], crun);
}

// ---------------- finalize ----------------
__global__ void k_final(const float* __restrict__ Wl, const float* __restrict__ bl,
                        float* __restrict__ out)
{
    int g = blockIdx.x;
    int d = threadIdx.x;
    __shared__ float red[128];
    __shared__ float xsh[128];
    float c = g_cntf[g];
    float pooled = g_sums[g * DD + d] / fmaxf(c, 1.f);
    red[d] = pooled * pooled;
    __syncthreads();
    for (int s = 64; s > 0; s >>= 1) {
        if (d < s) red[d] += red[d + s];
        __syncthreads();
    }
    float inv = 1.f / fmaxf(sqrtf(red[0]), 1e-12f);
    float xn = pooled * inv;
    out[g * DD + d] = xn;
    xsh[d] = xn;
    __syncthreads();
    if (d < CC) {
        float dot = 0.f, w2 = 0.f;
        for (int k = 0; k < DD; k++) {
            float w = Wl[d * DD + k];
            dot += xsh[k] * w;
            w2 += w * w;
        }
        out[GG * DD + g * CC + d] = dot / fmaxf(sqrtf(w2), 1e-12f) + bl[d];
    }
}

// ---------------- launch ----------------
extern "C" void kernel_launch(void* const* d_in, const int* in_sizes, int n_in,
                              void* d_out, int out_size)
{
    const float* x   = (const float*)d_in[0];
    const int*   ei  = (const int*)d_in[1];
    const int*   bat = (const int*)d_in[2];
    const float* W1r = (const float*)d_in[3];
    const float* b1  = (const float*)d_in[4];
    const float* W1x = (const float*)d_in[5];
    const float* W2  = (const float*)d_in[6];
    const float* b2  = (const float*)d_in[7];
    const float* W3  = (const float*)d_in[8];
    const float* b3  = (const float*)d_in[9];
    const float* Wl  = (const float*)d_in[10];
    const float* bl  = (const float*)d_in[11];
    float* out = (float*)d_out;
    const int* row = ei;
    const int* col = ei + EE;

    cudaFuncSetAttribute(k_gemm_mma, cudaFuncAttributeMaxDynamicSharedMemorySize, GSMEM);

    int gwarps = (NN * 32 + 255) / 256;
    int tblocks = (NN + 127) / 128;

    k_zero<<<(NN + 255) / 256, 256>>>();
    k_count<<<(EE + 255) / 256, 256>>>(col);
    k_scan<<<1, 1024>>>();
    k_fill<<<(EE + 255) / 256, 256>>>(row, col);
    k_gather_x<<<gwarps, 256>>>(x);                              // buf0 = sum_nbr x

    // conv1: buf1 = relu(buf0 @ W1r^T + x @ W1x^T + b1)
    k_gemm_mma<<<tblocks, 256, GSMEM>>>(x, 0, W1r, W1x, b1, 0, 1, 2, 1);
    // buf0 = dinv * (buf1 @ W2^T)
    k_gemm_mma<<<tblocks, 256, GSMEM>>>(nullptr, 1, W2, nullptr, nullptr, 1, 0, 1, 0);
    k_gather_norm<<<gwarps, 256>>>(0, 2, b2, 1);                 // buf2 = h2
    // buf0 = dinv * (buf2 @ W3^T)
    k_gemm_mma<<<tblocks, 256, GSMEM>>>(nullptr, 2, W3, nullptr, nullptr, 1, 0, 1, 0);
    k_gather_norm<<<gwarps, 256>>>(0, 1, b3, 0);                 // buf1 = h3
    k_pool<<<(NN + 511) / 512, 128>>>(bat, 1);
    k_final<<<GG, 128>>>(Wl, bl, out);
}